// round 15
// baseline (speedup 1.0000x reference)
#include <cuda_runtime.h>
#include <cuda_fp16.h>

#define R     5
#define TILE  32
#define HTR   42         // rows: TILE + 2*5
#define HTC   48         // cols loaded: halo -8..+7 (16B-aligned everywhere)
#define SXP   48         // sxy row stride in half2 (192B, 16B multiple)
#define HBP   44         // hb row stride in half2 (176B, 16B multiple)
#define NIMG  48         // 16 batch * 3 channels
#define L0_BLOCKS   12288u
#define TAIL_BLOCKS 4080u

// ---- compile-time float -> half(RN-ish) converter, duplicated to half2 bits ----
__host__ __device__ constexpr unsigned short f2h_rn(double x) {
    int e = 0;
    double m = x;
    while (m < 1.0)  { m *= 2.0; e--; }
    while (m >= 2.0) { m *= 0.5; e++; }
    int mant = (int)((m - 1.0) * 1024.0 + 0.5);
    int E = e + 15;
    if (mant == 1024) { mant = 0; E += 1; }
    return (unsigned short)((E << 10) | mant);
}
struct HTab { unsigned v[11]; };
__host__ __device__ constexpr HTab make_tab(double s) {
    HTab t{};
    const double w[11] = {
        0.0010283792, 0.0075987573, 0.0360007521, 0.1093607103, 0.2130055812,
        0.2660117310,
        0.2130055812, 0.1093607103, 0.0360007521, 0.0075987573, 0.0010283792 };
    for (int i = 0; i < 11; i++)
        t.v[i] = (unsigned)f2h_rn(w[i] * s) * 0x10001u;
    return t;
}
// Device accessors: local constexpr tables fold to immediates after unroll.
__device__ __forceinline__ unsigned wh1u(int t) {
    constexpr HTab T = make_tab(1.0);                   // pass-1 weights
    return T.v[t];
}
__device__ __forceinline__ unsigned whsu(int t) {
    constexpr HTab T = make_tab(0.70710678118654752);   // pass-2 (S,D): x 1/sqrt(2)
    return T.v[t];
}
__device__ __forceinline__ unsigned whpu(int t) {
    constexpr HTab T = make_tab(0.5);                   // pass-2 (P,Q): x 0.5
    return T.v[t];
}

__device__ __forceinline__ __half2 h2c(unsigned u) {
    __half2_raw r;
    r.x = (unsigned short)(u & 0xFFFFu);
    r.y = (unsigned short)(u >> 16);
    return r;
}
__device__ __forceinline__ __half2 h2zero() { return h2c(0u); }

// Pyramid in (s,d) half2 space.
__device__ __half2  g_pyrA[NIMG * 256 * 256];   // level 1
__device__ __half2  g_pyrB[NIMG * 128 * 128];   // level 2
__device__ __half2  g_pyrC[NIMG * 64 * 64];     // level 3
__device__ __half2  g_pyrD[NIMG * 32 * 32];     // level 4
__device__ double   g_acc[5];                   // zero-init; finisher re-zeroes
__device__ unsigned g_tick;                     // zero-init; finisher re-zeroes
__device__ unsigned g_imgdone[NIMG];            // zero-init; finisher re-zeroes

// One 32x32 SSIM tile, fp16 packed (s,d) conv, fp32 SSIM epilogue (R12-proven).
template<bool POOL, bool SD_IN>
__device__ __forceinline__ void ssim_tile(
    const float* __restrict__ X, const float* __restrict__ Y,     // SD_IN=false
    const __half2* __restrict__ XY,                               // SD_IN=true
    int H, int W, int tx, int ty, int img,
    double* __restrict__ acc,
    __half2* __restrict__ PA, __half2* __restrict__ PB,
    __half2* __restrict__ PC, __half2* __restrict__ PD)
{
    __shared__ __align__(16) __half2 sxy[HTR][SXP];   // (s, d)
    __shared__ __align__(16) __half2 hbSD[TILE][HBP]; // v-blurred (s, d)
    __shared__ __align__(16) __half2 hbPQ[TILE][HBP]; // v-blurred (s^2, d^2)
    __shared__ float wsum[8];

    const int tid  = threadIdx.x;
    const int base = img * H * W;
    const int r0   = ty * TILE - R;       // row halo: -5..+5
    const int c0   = tx * TILE - 8;       // col halo: -8..+7 (16B-aligned base)

    const bool interior = (r0 >= 0) && (r0 + HTR <= H) && (c0 >= 0) && (c0 + HTC <= W);

    // ---- load tile + halo ----
    if (interior) {
        if (SD_IN) {
            for (int i = tid; i < HTR * 12; i += 256) {
                int r = i / 12, c4 = i - r * 12;
                const float4* p = (const float4*)(XY + base + (r0 + r) * W + c0) + c4;
                *(float4*)&sxy[r][4 * c4] = *p;
            }
        } else {
            for (int i = tid; i < HTR * 12; i += 256) {
                int r = i / 12, c4 = i - r * 12;
                int gi = base + (r0 + r) * W + c0 + 4 * c4;
                float4 xa = *(const float4*)(X + gi);
                float4 ya = *(const float4*)(Y + gi);
                __half2 h0 = __floats2half2_rn(xa.x + ya.x, xa.x - ya.x);
                __half2 h1 = __floats2half2_rn(xa.y + ya.y, xa.y - ya.y);
                __half2 h2 = __floats2half2_rn(xa.z + ya.z, xa.z - ya.z);
                __half2 h3 = __floats2half2_rn(xa.w + ya.w, xa.w - ya.w);
                uint4 u;
                u.x = *(unsigned*)&h0; u.y = *(unsigned*)&h1;
                u.z = *(unsigned*)&h2; u.w = *(unsigned*)&h3;
                *(uint4*)&sxy[r][4 * c4] = u;
            }
        }
    } else {
        for (int i = tid; i < HTR * HTC; i += 256) {
            int r  = i / HTC, c = i - r * HTC;
            int gr = r0 + r, gc = c0 + c;
            __half2 hv = h2zero();
            if ((unsigned)gr < (unsigned)H && (unsigned)gc < (unsigned)W) {
                int gi = base + gr * W + gc;
                if (SD_IN) {
                    hv = XY[gi];
                } else {
                    float xv = X[gi], yv = Y[gi];
                    hv = __floats2half2_rn(xv + yv, xv - yv);
                }
            }
            sxy[r][c] = hv;
        }
    }
    __syncthreads();

    // ---- pass 1: vertical blur, 4 output rows per unit (336 units) ----
    for (int u = tid; u < 42 * 8; u += 256) {
        int c  = u % 42;
        int rb = (u / 42) * 4;
        __half2 aSD[4], aPQ[4];
#pragma unroll
        for (int k = 0; k < 4; k++) { aSD[k] = h2zero(); aPQ[k] = h2zero(); }
#pragma unroll
        for (int t = 0; t < 14; t++) {
            __half2 v  = sxy[rb + t][c + 3];
            __half2 v2 = __hmul2(v, v);
#pragma unroll
            for (int k = 0; k < 4; k++) {
                int tt = t - k;                 // compile-time after unroll
                if (tt >= 0 && tt <= 10) {
                    aSD[k] = __hfma2(h2c(wh1u(tt)), v,  aSD[k]);
                    aPQ[k] = __hfma2(h2c(wh1u(tt)), v2, aPQ[k]);
                }
            }
        }
#pragma unroll
        for (int k = 0; k < 4; k++) {
            hbSD[rb + k][c] = aSD[k];
            hbPQ[rb + k][c] = aPQ[k];
        }
    }
    __syncthreads();

    // ---- pass 2: horizontal blur + SSIM, 4 px/thread ----
    const int vr = tid >> 3;          // output row 0..31
    const int vc = (tid & 7) * 4;     // output col group (16B aligned)

    __half2 mSD[4], mPQ[4];
#pragma unroll
    for (int k = 0; k < 4; k++) { mSD[k] = h2zero(); mPQ[k] = h2zero(); }

    {   // (S, D) stream — 4 x LDS.128 covering 16 taps (14 used)
        __half2 vb[16];
        const uint4* p = (const uint4*)&hbSD[vr][vc];
#pragma unroll
        for (int q = 0; q < 4; q++) {
            uint4 a = p[q];
            vb[4 * q + 0] = h2c(a.x); vb[4 * q + 1] = h2c(a.y);
            vb[4 * q + 2] = h2c(a.z); vb[4 * q + 3] = h2c(a.w);
        }
#pragma unroll
        for (int t = 0; t < 14; t++)
#pragma unroll
            for (int k = 0; k < 4; k++) {
                int tt = t - k;
                if (tt >= 0 && tt <= 10)
                    mSD[k] = __hfma2(h2c(whsu(tt)), vb[t], mSD[k]);
            }
    }
    {   // (P, Q) stream — 4 x LDS.128
        __half2 vb[16];
        const uint4* p = (const uint4*)&hbPQ[vr][vc];
#pragma unroll
        for (int q = 0; q < 4; q++) {
            uint4 a = p[q];
            vb[4 * q + 0] = h2c(a.x); vb[4 * q + 1] = h2c(a.y);
            vb[4 * q + 2] = h2c(a.z); vb[4 * q + 3] = h2c(a.w);
        }
#pragma unroll
        for (int t = 0; t < 14; t++)
#pragma unroll
            for (int k = 0; k < 4; k++) {
                int tt = t - k;
                if (tt >= 0 && tt <= 10)
                    mPQ[k] = __hfma2(h2c(whpu(tt)), vb[t], mPQ[k]);
            }
    }

    // ---- SSIM epilogue, fp32 (R12-proven) ----
    const float C1 = 4.0e-4f;   // (0.01*2)^2
    const float C2 = 3.6e-3f;   // (0.03*2)^2
    float lsum = 0.f;
#pragma unroll
    for (int k = 0; k < 4; k++) {
        float2 sd = __half22float2(mSD[k]);   // (S/sqrt2, D/sqrt2)
        float2 pq = __half22float2(mPQ[k]);   // (P/2, Q/2)
        float S2 = sd.x * sd.x;               // S^2/2
        float D2 = sd.y * sd.y;               // D^2/2
        float sumSq = S2 + D2;                // mu1^2 + mu2^2
        float difSq = S2 - D2;                // 2*mu1*mu2
        float A1 = difSq + C1;
        float B1 = sumSq + C1;
        float A2 = (pq.x - pq.y) - difSq + C2;   // 2*sig12 + C2
        float B2 = (pq.x + pq.y) - sumSq + C2;   // sig1+sig2 + C2
        lsum += __fdividef(A1 * A2, B1 * B2 + 1e-8f);
    }

    // ---- block reduction -> one double atomic per block ----
#pragma unroll
    for (int o = 16; o > 0; o >>= 1)
        lsum += __shfl_xor_sync(0xFFFFFFFFu, lsum, o);
    if ((tid & 31) == 0) wsum[tid >> 5] = lsum;
    __syncthreads();          // hb arrays fully consumed beyond this point
    if (tid == 0) {
        float b = 0.f;
#pragma unroll
        for (int i = 0; i < 8; i++) b += wsum[i];
        atomicAdd(acc, (double)b);
    }

    // ---- fused full pyramid emission (L0 only): A, B, C, D patches ----
    if (POOL) {
        __half2* bufA = &hbSD[0][0];       // 16x16 scratch (256 half2)
        __half2* bufB = &hbPQ[0][0];       // 8x8 scratch
        __half2* bufC = &hbSD[8][0];       // 4x4 scratch (past bufA's 256)

        {   // input(central 32x32, sxy cols 8..39) -> A 16x16
            int pr = tid >> 4, pc = tid & 15;
            int rr = R + 2 * pr, cc = 8 + 2 * pc;
            float2 a = __half22float2(sxy[rr][cc]);
            float2 b = __half22float2(sxy[rr][cc + 1]);
            float2 c = __half22float2(sxy[rr + 1][cc]);
            float2 d = __half22float2(sxy[rr + 1][cc + 1]);
            __half2 av = __floats2half2_rn(0.25f * (a.x + b.x + c.x + d.x),
                                           0.25f * (a.y + b.y + c.y + d.y));
            PA[img * 256 * 256 + (ty * 16 + pr) * 256 + tx * 16 + pc] = av;
            bufA[pr * 16 + pc] = av;
        }
        __syncthreads();
        if (tid < 64) {   // A -> B 8x8
            int r = tid >> 3, c = tid & 7;
            float2 a = __half22float2(bufA[(2 * r) * 16 + 2 * c]);
            float2 b = __half22float2(bufA[(2 * r) * 16 + 2 * c + 1]);
            float2 d = __half22float2(bufA[(2 * r + 1) * 16 + 2 * c]);
            float2 e = __half22float2(bufA[(2 * r + 1) * 16 + 2 * c + 1]);
            __half2 bv = __floats2half2_rn(0.25f * (a.x + b.x + d.x + e.x),
                                           0.25f * (a.y + b.y + d.y + e.y));
            PB[img * 128 * 128 + (ty * 8 + r) * 128 + tx * 8 + c] = bv;
            bufB[r * 8 + c] = bv;
        }
        __syncthreads();
        if (tid < 16) {   // B -> C 4x4
            int r = tid >> 2, c = tid & 3;
            float2 a = __half22float2(bufB[(2 * r) * 8 + 2 * c]);
            float2 b = __half22float2(bufB[(2 * r) * 8 + 2 * c + 1]);
            float2 d = __half22float2(bufB[(2 * r + 1) * 8 + 2 * c]);
            float2 e = __half22float2(bufB[(2 * r + 1) * 8 + 2 * c + 1]);
            __half2 cv = __floats2half2_rn(0.25f * (a.x + b.x + d.x + e.x),
                                           0.25f * (a.y + b.y + d.y + e.y));
            PC[img * 64 * 64 + (ty * 4 + r) * 64 + tx * 4 + c] = cv;
            bufC[r * 4 + c] = cv;
        }
        __syncthreads();
        if (tid < 4) {    // C -> D 2x2
            int r = tid >> 1, c = tid & 1;
            float2 a = __half22float2(bufC[(2 * r) * 4 + 2 * c]);
            float2 b = __half22float2(bufC[(2 * r) * 4 + 2 * c + 1]);
            float2 d = __half22float2(bufC[(2 * r + 1) * 4 + 2 * c]);
            float2 e = __half22float2(bufC[(2 * r + 1) * 4 + 2 * c + 1]);
            PD[img * 32 * 32 + (ty * 2 + r) * 32 + tx * 2 + c] =
                __floats2half2_rn(0.25f * (a.x + b.x + d.x + e.x),
                                  0.25f * (a.y + b.y + d.y + e.y));
        }
    }
}

// Fused single launch: blocks [0, 12288) = L0 tiles (SSIM + pyramid emission,
// then signal per-image counter); blocks [12288, 16368) = tail tiles (spin on
// their image's counter, then SSIM of levels 1..4); last tail block finishes.
__global__ __launch_bounds__(256, 6) void ssim_fused_kernel(
    const float* __restrict__ X, const float* __restrict__ Y,
    __half2* __restrict__ PA, __half2* __restrict__ PB,
    __half2* __restrict__ PC, __half2* __restrict__ PD,
    double* __restrict__ acc, float* __restrict__ out)
{
    const unsigned bid = blockIdx.x;
    const int tid = threadIdx.x;

    if (bid < L0_BLOCKS) {
        // ---- L0 producer path ----
        int img = bid >> 8;
        int r   = bid & 255;
        int tx  = r & 15, ty = r >> 4;
        ssim_tile<true, false>(X, Y, nullptr, 512, 512, tx, ty, img, acc,
                               PA, PB, PC, PD);
        __syncthreads();                  // all pyramid patch writes done
        if (tid == 0) {
            __threadfence();
            atomicAdd(&g_imgdone[img], 1u);
        }
    } else {
        // ---- tail consumer path ----
        unsigned b = bid - L0_BLOCKS;
        int img = b / 85;
        int t   = b - img * 85;
        const __half2* XY;
        int H, tx, ty, lvl;
        if (t < 64)      { lvl = 1; H = 256; tx = t & 7; ty = t >> 3;               XY = PA; }
        else if (t < 80) { lvl = 2; H = 128; int q = t - 64; tx = q & 3; ty = q >> 2; XY = PB; }
        else if (t < 84) { lvl = 3; H = 64;  int q = t - 80; tx = q & 1; ty = q >> 1; XY = PC; }
        else             { lvl = 4; H = 32;  tx = 0; ty = 0;                          XY = PD; }

        // spin until this image's pyramid is complete (producers never wait)
        if (tid == 0) {
            unsigned v;
            do {
                asm volatile("ld.acquire.gpu.u32 %0, [%1];"
                             : "=r"(v) : "l"(&g_imgdone[img]) : "memory");
            } while (v < 256u);
        }
        __syncthreads();

        ssim_tile<false, true>(nullptr, nullptr, XY, H, H, tx, ty, img,
                               acc + lvl, nullptr, nullptr, nullptr, nullptr);

        // ---- fused finisher: last tail block computes loss, resets state ----
        if (tid == 0) {
            __threadfence();
            unsigned tk = atomicAdd(&g_tick, 1u);
            if (tk == TAIL_BLOCKS - 1u) {
                const double w[5] = {0.0448, 0.2856, 0.3001, 0.2363, 0.1333};
                const double wsumv = 1.0001;  // reference normalizes by weight sum
                double cnt = (double)NIMG * 512.0 * 512.0;
                double m = 0.0;
#pragma unroll
                for (int l = 0; l < 5; l++) {
                    double a = atomicAdd(&g_acc[l], 0.0);   // coherent read
                    m += (w[l] / wsumv) * (a / cnt);
                    cnt *= 0.25;
                    atomicExch((unsigned long long*)&g_acc[l], 0ull);  // reset
                }
                out[0] = (float)(1.0 - m);
                for (int i = 0; i < NIMG; i++)
                    atomicExch(&g_imgdone[i], 0u);           // reset flags
                atomicExch(&g_tick, 0u);                     // reset ticket
            }
        }
    }
}

extern "C" void kernel_launch(void* const* d_in, const int* in_sizes, int n_in,
                              void* d_out, int out_size)
{
    (void)in_sizes; (void)n_in; (void)out_size;
    const float* pred   = (const float*)d_in[0];
    const float* target = (const float*)d_in[1];
    float* out = (float*)d_out;

    __half2 *pA, *pB, *pC, *pD;
    double* acc;
    cudaGetSymbolAddress((void**)&pA, g_pyrA);
    cudaGetSymbolAddress((void**)&pB, g_pyrB);
    cudaGetSymbolAddress((void**)&pC, g_pyrC);
    cudaGetSymbolAddress((void**)&pD, g_pyrD);
    cudaGetSymbolAddress((void**)&acc, g_acc);

    ssim_fused_kernel<<<L0_BLOCKS + TAIL_BLOCKS, 256>>>(
        pred, target, pA, pB, pC, pD, acc, out);
}

// round 16
// speedup vs baseline: 1.1791x; 1.1791x over previous
#include <cuda_runtime.h>
#include <cuda_fp16.h>

#define R     5
#define TILE  32
#define HTR   42         // rows: TILE + 2*5
#define HTC   48         // cols loaded: halo -8..+7 (16B-aligned everywhere)
#define SXP   48         // sxy row stride in half2 (192B, 16B multiple)
#define HBP   44         // hb row stride in half2 (176B, 16B multiple)
#define NIMG  48         // 16 batch * 3 channels
#define L0_BLOCKS   12288u
#define TAIL_BLOCKS 4080u

// ---- compile-time float -> half(RN-ish) converter, duplicated to half2 bits ----
__host__ __device__ constexpr unsigned short f2h_rn(double x) {
    int e = 0;
    double m = x;
    while (m < 1.0)  { m *= 2.0; e--; }
    while (m >= 2.0) { m *= 0.5; e++; }
    int mant = (int)((m - 1.0) * 1024.0 + 0.5);
    int E = e + 15;
    if (mant == 1024) { mant = 0; E += 1; }
    return (unsigned short)((E << 10) | mant);
}
struct HTab { unsigned v[11]; };
__host__ __device__ constexpr HTab make_tab(double s) {
    HTab t{};
    const double w[11] = {
        0.0010283792, 0.0075987573, 0.0360007521, 0.1093607103, 0.2130055812,
        0.2660117310,
        0.2130055812, 0.1093607103, 0.0360007521, 0.0075987573, 0.0010283792 };
    for (int i = 0; i < 11; i++)
        t.v[i] = (unsigned)f2h_rn(w[i] * s) * 0x10001u;
    return t;
}
// Device accessors: local constexpr tables fold to immediates after unroll.
__device__ __forceinline__ unsigned wh1u(int t) {
    constexpr HTab T = make_tab(1.0);                   // pass-1 weights
    return T.v[t];
}
__device__ __forceinline__ unsigned whsu(int t) {
    constexpr HTab T = make_tab(0.70710678118654752);   // pass-2 (S,D): x 1/sqrt(2)
    return T.v[t];
}
__device__ __forceinline__ unsigned whpu(int t) {
    constexpr HTab T = make_tab(0.5);                   // pass-2 (P,Q): x 0.5
    return T.v[t];
}

__device__ __forceinline__ __half2 h2c(unsigned u) {
    __half2_raw r;
    r.x = (unsigned short)(u & 0xFFFFu);
    r.y = (unsigned short)(u >> 16);
    return r;
}
__device__ __forceinline__ __half2 h2zero() { return h2c(0u); }

// Pyramid in (s,d) half2 space.
__device__ __half2  g_pyrA[NIMG * 256 * 256];   // level 1
__device__ __half2  g_pyrB[NIMG * 128 * 128];   // level 2
__device__ __half2  g_pyrC[NIMG * 64 * 64];     // level 3
__device__ __half2  g_pyrD[NIMG * 32 * 32];     // level 4
__device__ double   g_acc[5];                   // zero-init; finisher re-zeroes
__device__ unsigned g_tick;                     // zero-init; finisher re-zeroes
__device__ unsigned g_imgdone[NIMG];            // zero-init; finisher re-zeroes

typedef __half2 (*SxyP)[SXP];
typedef __half2 (*HbP)[HBP];

// One 32x32 SSIM tile, fp16 packed (s,d) conv, fp32 SSIM epilogue.
// Shared arrays are provided by the caller so both call sites share ONE
// allocation (scoped __shared__ in each instantiation doubled smem in R15).
template<bool POOL, bool SD_IN>
__device__ __forceinline__ void ssim_tile(
    SxyP sxy, HbP hbSD, HbP hbPQ, float* wsum,
    const float* __restrict__ X, const float* __restrict__ Y,     // SD_IN=false
    const __half2* __restrict__ XY,                               // SD_IN=true
    int H, int W, int tx, int ty, int img,
    double* __restrict__ acc,
    __half2* __restrict__ PA, __half2* __restrict__ PB,
    __half2* __restrict__ PC, __half2* __restrict__ PD)
{
    const int tid  = threadIdx.x;
    const int base = img * H * W;
    const int r0   = ty * TILE - R;       // row halo: -5..+5
    const int c0   = tx * TILE - 8;       // col halo: -8..+7 (16B-aligned base)

    const bool interior = (r0 >= 0) && (r0 + HTR <= H) && (c0 >= 0) && (c0 + HTC <= W);

    // ---- load tile + halo ----
    if (interior) {
        if (SD_IN) {
            for (int i = tid; i < HTR * 12; i += 256) {
                int r = i / 12, c4 = i - r * 12;
                const float4* p = (const float4*)(XY + base + (r0 + r) * W + c0) + c4;
                *(float4*)&sxy[r][4 * c4] = *p;
            }
        } else {
            for (int i = tid; i < HTR * 12; i += 256) {
                int r = i / 12, c4 = i - r * 12;
                int gi = base + (r0 + r) * W + c0 + 4 * c4;
                float4 xa = *(const float4*)(X + gi);
                float4 ya = *(const float4*)(Y + gi);
                __half2 h0 = __floats2half2_rn(xa.x + ya.x, xa.x - ya.x);
                __half2 h1 = __floats2half2_rn(xa.y + ya.y, xa.y - ya.y);
                __half2 h2 = __floats2half2_rn(xa.z + ya.z, xa.z - ya.z);
                __half2 h3 = __floats2half2_rn(xa.w + ya.w, xa.w - ya.w);
                uint4 u;
                u.x = *(unsigned*)&h0; u.y = *(unsigned*)&h1;
                u.z = *(unsigned*)&h2; u.w = *(unsigned*)&h3;
                *(uint4*)&sxy[r][4 * c4] = u;
            }
        }
    } else {
        for (int i = tid; i < HTR * HTC; i += 256) {
            int r  = i / HTC, c = i - r * HTC;
            int gr = r0 + r, gc = c0 + c;
            __half2 hv = h2zero();
            if ((unsigned)gr < (unsigned)H && (unsigned)gc < (unsigned)W) {
                int gi = base + gr * W + gc;
                if (SD_IN) {
                    hv = XY[gi];
                } else {
                    float xv = X[gi], yv = Y[gi];
                    hv = __floats2half2_rn(xv + yv, xv - yv);
                }
            }
            sxy[r][c] = hv;
        }
    }
    __syncthreads();

    // ---- pass 1: vertical blur, 4 output rows per unit (336 units) ----
    for (int u = tid; u < 42 * 8; u += 256) {
        int c  = u % 42;
        int rb = (u / 42) * 4;
        __half2 aSD[4], aPQ[4];
#pragma unroll
        for (int k = 0; k < 4; k++) { aSD[k] = h2zero(); aPQ[k] = h2zero(); }
#pragma unroll
        for (int t = 0; t < 14; t++) {
            __half2 v  = sxy[rb + t][c + 3];
            __half2 v2 = __hmul2(v, v);
#pragma unroll
            for (int k = 0; k < 4; k++) {
                int tt = t - k;                 // compile-time after unroll
                if (tt >= 0 && tt <= 10) {
                    aSD[k] = __hfma2(h2c(wh1u(tt)), v,  aSD[k]);
                    aPQ[k] = __hfma2(h2c(wh1u(tt)), v2, aPQ[k]);
                }
            }
        }
#pragma unroll
        for (int k = 0; k < 4; k++) {
            hbSD[rb + k][c] = aSD[k];
            hbPQ[rb + k][c] = aPQ[k];
        }
    }
    __syncthreads();

    // ---- pass 2: horizontal blur + SSIM, 4 px/thread ----
    const int vr = tid >> 3;          // output row 0..31
    const int vc = (tid & 7) * 4;     // output col group (16B aligned)

    __half2 mSD[4], mPQ[4];
#pragma unroll
    for (int k = 0; k < 4; k++) { mSD[k] = h2zero(); mPQ[k] = h2zero(); }

    {   // (S, D) stream — 4 x LDS.128 covering 16 taps (14 used)
        __half2 vb[16];
        const uint4* p = (const uint4*)&hbSD[vr][vc];
#pragma unroll
        for (int q = 0; q < 4; q++) {
            uint4 a = p[q];
            vb[4 * q + 0] = h2c(a.x); vb[4 * q + 1] = h2c(a.y);
            vb[4 * q + 2] = h2c(a.z); vb[4 * q + 3] = h2c(a.w);
        }
#pragma unroll
        for (int t = 0; t < 14; t++)
#pragma unroll
            for (int k = 0; k < 4; k++) {
                int tt = t - k;
                if (tt >= 0 && tt <= 10)
                    mSD[k] = __hfma2(h2c(whsu(tt)), vb[t], mSD[k]);
            }
    }
    {   // (P, Q) stream — 4 x LDS.128
        __half2 vb[16];
        const uint4* p = (const uint4*)&hbPQ[vr][vc];
#pragma unroll
        for (int q = 0; q < 4; q++) {
            uint4 a = p[q];
            vb[4 * q + 0] = h2c(a.x); vb[4 * q + 1] = h2c(a.y);
            vb[4 * q + 2] = h2c(a.z); vb[4 * q + 3] = h2c(a.w);
        }
#pragma unroll
        for (int t = 0; t < 14; t++)
#pragma unroll
            for (int k = 0; k < 4; k++) {
                int tt = t - k;
                if (tt >= 0 && tt <= 10)
                    mPQ[k] = __hfma2(h2c(whpu(tt)), vb[t], mPQ[k]);
            }
    }

    // ---- SSIM epilogue, fp32 (R12-proven) ----
    const float C1 = 4.0e-4f;   // (0.01*2)^2
    const float C2 = 3.6e-3f;   // (0.03*2)^2
    float lsum = 0.f;
#pragma unroll
    for (int k = 0; k < 4; k++) {
        float2 sd = __half22float2(mSD[k]);   // (S/sqrt2, D/sqrt2)
        float2 pq = __half22float2(mPQ[k]);   // (P/2, Q/2)
        float S2 = sd.x * sd.x;               // S^2/2
        float D2 = sd.y * sd.y;               // D^2/2
        float sumSq = S2 + D2;                // mu1^2 + mu2^2
        float difSq = S2 - D2;                // 2*mu1*mu2
        float A1 = difSq + C1;
        float B1 = sumSq + C1;
        float A2 = (pq.x - pq.y) - difSq + C2;   // 2*sig12 + C2
        float B2 = (pq.x + pq.y) - sumSq + C2;   // sig1+sig2 + C2
        lsum += __fdividef(A1 * A2, B1 * B2 + 1e-8f);
    }

    // ---- block reduction -> one double atomic per block ----
#pragma unroll
    for (int o = 16; o > 0; o >>= 1)
        lsum += __shfl_xor_sync(0xFFFFFFFFu, lsum, o);
    if ((tid & 31) == 0) wsum[tid >> 5] = lsum;
    __syncthreads();          // hb arrays fully consumed beyond this point
    if (tid == 0) {
        float b = 0.f;
#pragma unroll
        for (int i = 0; i < 8; i++) b += wsum[i];
        atomicAdd(acc, (double)b);
    }

    // ---- fused full pyramid emission (L0 only): A, B, C, D patches ----
    if (POOL) {
        __half2* bufA = &hbSD[0][0];       // 16x16 scratch (256 half2)
        __half2* bufB = &hbPQ[0][0];       // 8x8 scratch
        __half2* bufC = &hbSD[8][0];       // 4x4 scratch (past bufA's 256)

        {   // input(central 32x32, sxy cols 8..39) -> A 16x16
            int pr = tid >> 4, pc = tid & 15;
            int rr = R + 2 * pr, cc = 8 + 2 * pc;
            float2 a = __half22float2(sxy[rr][cc]);
            float2 b = __half22float2(sxy[rr][cc + 1]);
            float2 c = __half22float2(sxy[rr + 1][cc]);
            float2 d = __half22float2(sxy[rr + 1][cc + 1]);
            __half2 av = __floats2half2_rn(0.25f * (a.x + b.x + c.x + d.x),
                                           0.25f * (a.y + b.y + c.y + d.y));
            PA[img * 256 * 256 + (ty * 16 + pr) * 256 + tx * 16 + pc] = av;
            bufA[pr * 16 + pc] = av;
        }
        __syncthreads();
        if (tid < 64) {   // A -> B 8x8
            int r = tid >> 3, c = tid & 7;
            float2 a = __half22float2(bufA[(2 * r) * 16 + 2 * c]);
            float2 b = __half22float2(bufA[(2 * r) * 16 + 2 * c + 1]);
            float2 d = __half22float2(bufA[(2 * r + 1) * 16 + 2 * c]);
            float2 e = __half22float2(bufA[(2 * r + 1) * 16 + 2 * c + 1]);
            __half2 bv = __floats2half2_rn(0.25f * (a.x + b.x + d.x + e.x),
                                           0.25f * (a.y + b.y + d.y + e.y));
            PB[img * 128 * 128 + (ty * 8 + r) * 128 + tx * 8 + c] = bv;
            bufB[r * 8 + c] = bv;
        }
        __syncthreads();
        if (tid < 16) {   // B -> C 4x4
            int r = tid >> 2, c = tid & 3;
            float2 a = __half22float2(bufB[(2 * r) * 8 + 2 * c]);
            float2 b = __half22float2(bufB[(2 * r) * 8 + 2 * c + 1]);
            float2 d = __half22float2(bufB[(2 * r + 1) * 8 + 2 * c]);
            float2 e = __half22float2(bufB[(2 * r + 1) * 8 + 2 * c + 1]);
            __half2 cv = __floats2half2_rn(0.25f * (a.x + b.x + d.x + e.x),
                                           0.25f * (a.y + b.y + d.y + e.y));
            PC[img * 64 * 64 + (ty * 4 + r) * 64 + tx * 4 + c] = cv;
            bufC[r * 4 + c] = cv;
        }
        __syncthreads();
        if (tid < 4) {    // C -> D 2x2
            int r = tid >> 1, c = tid & 1;
            float2 a = __half22float2(bufC[(2 * r) * 4 + 2 * c]);
            float2 b = __half22float2(bufC[(2 * r) * 4 + 2 * c + 1]);
            float2 d = __half22float2(bufC[(2 * r + 1) * 4 + 2 * c]);
            float2 e = __half22float2(bufC[(2 * r + 1) * 4 + 2 * c + 1]);
            PD[img * 32 * 32 + (ty * 2 + r) * 32 + tx * 2 + c] =
                __floats2half2_rn(0.25f * (a.x + b.x + d.x + e.x),
                                  0.25f * (a.y + b.y + d.y + e.y));
        }
    }
}

// Fused single launch: blocks [0, 12288) = L0 tiles (SSIM + pyramid emission,
// then signal per-image counter); blocks [12288, 16368) = tail tiles (spin on
// their image's counter, then SSIM of levels 1..4); last tail block finishes.
__global__ __launch_bounds__(256, 6) void ssim_fused_kernel(
    const float* __restrict__ X, const float* __restrict__ Y,
    __half2* __restrict__ PA, __half2* __restrict__ PB,
    __half2* __restrict__ PC, __half2* __restrict__ PD,
    double* __restrict__ acc, float* __restrict__ out)
{
    // ONE shared allocation for both paths (kernel scope, passed by pointer).
    __shared__ __align__(16) __half2 s_sxy[HTR][SXP];
    __shared__ __align__(16) __half2 s_hbSD[TILE][HBP];
    __shared__ __align__(16) __half2 s_hbPQ[TILE][HBP];
    __shared__ float s_wsum[8];

    const unsigned bid = blockIdx.x;
    const int tid = threadIdx.x;

    if (bid < L0_BLOCKS) {
        // ---- L0 producer path ----
        int img = bid >> 8;
        int r   = bid & 255;
        int tx  = r & 15, ty = r >> 4;
        ssim_tile<true, false>(s_sxy, s_hbSD, s_hbPQ, s_wsum,
                               X, Y, nullptr, 512, 512, tx, ty, img, acc,
                               PA, PB, PC, PD);
        __syncthreads();                  // all pyramid patch writes done
        if (tid == 0) {
            __threadfence();
            atomicAdd(&g_imgdone[img], 1u);
        }
    } else {
        // ---- tail consumer path ----
        unsigned b = bid - L0_BLOCKS;
        int img = b / 85;
        int t   = b - img * 85;
        const __half2* XY;
        int H, tx, ty, lvl;
        if (t < 64)      { lvl = 1; H = 256; tx = t & 7; ty = t >> 3;                 XY = PA; }
        else if (t < 80) { lvl = 2; H = 128; int q = t - 64; tx = q & 3; ty = q >> 2; XY = PB; }
        else if (t < 84) { lvl = 3; H = 64;  int q = t - 80; tx = q & 1; ty = q >> 1; XY = PC; }
        else             { lvl = 4; H = 32;  tx = 0; ty = 0;                          XY = PD; }

        // spin until this image's pyramid is complete (producers never wait)
        if (tid == 0) {
            unsigned v;
            do {
                asm volatile("ld.acquire.gpu.u32 %0, [%1];"
                             : "=r"(v) : "l"(&g_imgdone[img]) : "memory");
            } while (v < 256u);
        }
        __syncthreads();

        ssim_tile<false, true>(s_sxy, s_hbSD, s_hbPQ, s_wsum,
                               nullptr, nullptr, XY, H, H, tx, ty, img,
                               acc + lvl, nullptr, nullptr, nullptr, nullptr);

        // ---- fused finisher: last tail block computes loss, resets state ----
        if (tid == 0) {
            __threadfence();
            unsigned tk = atomicAdd(&g_tick, 1u);
            if (tk == TAIL_BLOCKS - 1u) {
                const double w[5] = {0.0448, 0.2856, 0.3001, 0.2363, 0.1333};
                const double wsumv = 1.0001;  // reference normalizes by weight sum
                double cnt = (double)NIMG * 512.0 * 512.0;
                double m = 0.0;
#pragma unroll
                for (int l = 0; l < 5; l++) {
                    double a = atomicAdd(&g_acc[l], 0.0);   // coherent read
                    m += (w[l] / wsumv) * (a / cnt);
                    cnt *= 0.25;
                    atomicExch((unsigned long long*)&g_acc[l], 0ull);  // reset
                }
                out[0] = (float)(1.0 - m);
                for (int i = 0; i < NIMG; i++)
                    atomicExch(&g_imgdone[i], 0u);           // reset flags
                atomicExch(&g_tick, 0u);                     // reset ticket
            }
        }
    }
}

extern "C" void kernel_launch(void* const* d_in, const int* in_sizes, int n_in,
                              void* d_out, int out_size)
{
    (void)in_sizes; (void)n_in; (void)out_size;
    const float* pred   = (const float*)d_in[0];
    const float* target = (const float*)d_in[1];
    float* out = (float*)d_out;

    __half2 *pA, *pB, *pC, *pD;
    double* acc;
    cudaGetSymbolAddress((void**)&pA, g_pyrA);
    cudaGetSymbolAddress((void**)&pB, g_pyrB);
    cudaGetSymbolAddress((void**)&pC, g_pyrC);
    cudaGetSymbolAddress((void**)&pD, g_pyrD);
    cudaGetSymbolAddress((void**)&acc, g_acc);

    ssim_fused_kernel<<<L0_BLOCKS + TAIL_BLOCKS, 256>>>(
        pred, target, pA, pB, pC, pD, acc, out);
}